// round 6
// baseline (speedup 1.0000x reference)
#include <cuda_runtime.h>
#include <cuda_bf16.h>

#define B_   8
#define C_   64
#define O_   64
#define H_   128
#define W_   128
#define HW_  16384
#define PAD_ 3
#define R_   49
#define HSTR 48                 // halo row stride (floats): conflict-free LDS.128 phases
#define CH_STRIDE (22 * HSTR)   // 1056 floats per halo channel

// Scratch (device globals)
__device__ float g_y[B_ * C_ * HW_];     // y = (W1^T W2) x
__device__ float g_v[B_ * C_ * HW_];     // v = W3 x
__device__ float g_M[64 * 64];           // M = W1^T W2

// -------------------- f32x2 helpers (qkv only) --------------------
__device__ __forceinline__ unsigned long long pk2(float lo, float hi) {
    unsigned long long r;
    asm("mov.b64 %0, {%1, %2};" : "=l"(r) : "f"(lo), "f"(hi));
    return r;
}
__device__ __forceinline__ void fma2(unsigned long long& d,
                                     unsigned long long a, unsigned long long b) {
    asm("fma.rn.f32x2 %0, %1, %2, %0;" : "+l"(d) : "l"(a), "l"(b));
}
__device__ __forceinline__ void upk2(unsigned long long v, float& lo, float& hi) {
    asm("mov.b64 {%0, %1}, %2;" : "=f"(lo), "=f"(hi) : "l"(v));
}

// ---------------------------------------------------------------------------
// Kernel 0: M = W1^T W2   (64x64x64)
// ---------------------------------------------------------------------------
__global__ __launch_bounds__(256) void mat_kernel(
    const float* __restrict__ W1, const float* __restrict__ W2)
{
    __shared__ float s1[4096], s2[4096];
    const int tx = threadIdx.x;
    for (int i = tx; i < 4096; i += 256) { s1[i] = W1[i]; s2[i] = W2[i]; }
    __syncthreads();

    const int c   = tx >> 2;
    const int cp0 = (tx & 3) * 16;
    float acc[16];
#pragma unroll
    for (int j = 0; j < 16; j++) acc[j] = 0.0f;

    for (int o = 0; o < 64; o++) {
        const float a = s1[o * 64 + c];
#pragma unroll
        for (int j = 0; j < 16; j++)
            acc[j] = fmaf(a, s2[o * 64 + cp0 + j], acc[j]);
    }
#pragma unroll
    for (int j = 0; j < 16; j++) g_M[c * 64 + cp0 + j] = acc[j];
}

// ---------------------------------------------------------------------------
// Kernel 1: y = M x (z=0), v = W3 x (z=1). f32x2 packed over out-pairs.
// grid (HW/128, B, 2), 256 threads, one matrix per block (low reg pressure).
// ---------------------------------------------------------------------------
__device__ __forceinline__ int wswz(int c, int o) {
    return c * 64 + (o ^ ((c << 1) & 63));
}

__global__ __launch_bounds__(256) void qkv_kernel(
    const float* __restrict__ x, const float* __restrict__ W3)
{
    __shared__ __align__(16) float sX[64 * 128];   // 32 KB
    __shared__ __align__(16) float sWp[64 * 64];   // 16 KB

    const int b = blockIdx.y, z = blockIdx.z;
    const float* Wm = (z == 0) ? g_M : W3;
    float* outp     = (z == 0) ? g_y : g_v;

    const int tx = threadIdx.x;
    const int n0 = blockIdx.x * 128;

    for (int i = tx; i < 4096; i += 256) {
        const int o = i >> 6, c = i & 63;
        sWp[wswz(c, o)] = Wm[i];
    }
    const float* xb = x + (size_t)b * C_ * HW_ + n0;
    for (int i = tx; i < 2048; i += 256) {
        const int c = i >> 5, j = i & 31;
        *(float4*)&sX[c * 128 + j * 4] = *(const float4*)(xb + (size_t)c * HW_ + j * 4);
    }
    __syncthreads();

    const int pp = tx & 31;
    const int oo = (tx >> 5) * 8;

    unsigned long long acc[4][4];
#pragma unroll
    for (int p = 0; p < 4; p++)
#pragma unroll
        for (int j = 0; j < 4; j++) acc[p][j] = 0ULL;

#pragma unroll 8
    for (int c = 0; c < 64; c++) {
        const float2 xa = *(const float2*)&sX[c * 128 + 2 * pp];
        const float2 xc = *(const float2*)&sX[c * 128 + 64 + 2 * pp];
        const unsigned long long d0 = pk2(xa.x, xa.x);
        const unsigned long long d1 = pk2(xa.y, xa.y);
        const unsigned long long d2 = pk2(xc.x, xc.x);
        const unsigned long long d3 = pk2(xc.y, xc.y);
#pragma unroll
        for (int j = 0; j < 4; j++) {
            const unsigned long long w2 =
                *(const unsigned long long*)&sWp[wswz(c, oo + 2 * j)];
            fma2(acc[0][j], w2, d0);
            fma2(acc[1][j], w2, d1);
            fma2(acc[2][j], w2, d2);
            fma2(acc[3][j], w2, d3);
        }
    }

    float* ob = outp + (size_t)b * O_ * HW_ + n0;
#pragma unroll
    for (int j = 0; j < 4; j++) {
        float a0, a1, b0, b1, c0, c1, d0, d1;
        upk2(acc[0][j], a0, a1);
        upk2(acc[1][j], b0, b1);
        upk2(acc[2][j], c0, c1);
        upk2(acc[3][j], d0, d1);
        const int o = oo + 2 * j;
        *(float2*)(ob + (size_t)o * HW_ + 2 * pp)            = make_float2(a0, b0);
        *(float2*)(ob + (size_t)o * HW_ + 64 + 2 * pp)       = make_float2(c0, d0);
        *(float2*)(ob + (size_t)(o + 1) * HW_ + 2 * pp)      = make_float2(a1, b1);
        *(float2*)(ob + (size_t)(o + 1) * HW_ + 64 + 2 * pp) = make_float2(c1, d1);
    }
}

// ---------------------------------------------------------------------------
// Halo fill: 8 channels of [22 x 22] zero-padded tile, stride HSTR. 256 thr.
// ---------------------------------------------------------------------------
__device__ __forceinline__ void fill_halo(
    float* sH, const float* __restrict__ src, int ch0, int h0, int w0, int tx)
{
    for (int idx = tx; idx < 8 * 484; idx += 256) {
        const int cc  = idx / 484;
        const int rem = idx - cc * 484;
        const int r   = rem / 22;
        const int col = rem - r * 22;
        const int hh  = h0 + r - PAD_;
        const int ww  = w0 + col - PAD_;
        float v = 0.0f;
        if (hh >= 0 && hh < H_ && ww >= 0 && ww < W_)
            v = src[(size_t)(ch0 + cc) * HW_ + hh * W_ + ww];
        sH[cc * CH_STRIDE + r * HSTR + col] = v;
    }
}

// Load 12-float window as 3 aligned LDS.128.
__device__ __forceinline__ void load_win(float* win, const float* rp) {
    const float4 A = *(const float4*)(rp);
    const float4 Bv = *(const float4*)(rp + 4);
    const float4 Cv = *(const float4*)(rp + 8);
    win[0] = A.x;  win[1] = A.y;  win[2] = A.z;  win[3] = A.w;
    win[4] = Bv.x; win[5] = Bv.y; win[6] = Bv.z; win[7] = Bv.w;
    win[8] = Cv.x; win[9] = Cv.y; win[10] = Cv.z; win[11] = Cv.w;
}

// ---------------------------------------------------------------------------
// Fused attention kernel: scores + softmax + weighting, no g_wt round trip.
// 16x16 tile, 256 thr = 64 quads (4 aligned px) x 4 dh-groups (2,2,2,1 rows).
// ---------------------------------------------------------------------------
template<int NDH, int DH0>
__device__ __forceinline__ void score_accum(
    float s[][4], const float* sH, const float* sX, int quad, int py, int qx4)
{
#pragma unroll
    for (int cc = 0; cc < 8; cc++) {
        const float4 q4 = *(const float4*)&sX[cc * 256 + 4 * quad];
        const float* rowb = sH + cc * CH_STRIDE + (py + DH0) * HSTR + qx4;
#pragma unroll
        for (int d = 0; d < NDH; d++) {
            float win[12];
            load_win(win, rowb + d * HSTR);
#pragma unroll
            for (int dw = 0; dw < 7; dw++) {
                s[d * 7 + dw][0] = fmaf(q4.x, win[dw + 0], s[d * 7 + dw][0]);
                s[d * 7 + dw][1] = fmaf(q4.y, win[dw + 1], s[d * 7 + dw][1]);
                s[d * 7 + dw][2] = fmaf(q4.z, win[dw + 2], s[d * 7 + dw][2]);
                s[d * 7 + dw][3] = fmaf(q4.w, win[dw + 3], s[d * 7 + dw][3]);
            }
        }
    }
}

// Phase B: one output channel at a time (4 live acc regs), flush to pbuf.
template<int NDH, int DH0>
__device__ __forceinline__ void weight_chunk(
    const float wt[][4], const float* sH, float4* pbuf,
    int g, int quad, int py, int qx4)
{
#pragma unroll
    for (int o = 0; o < 8; o++) {
        float a0 = 0.f, a1 = 0.f, a2 = 0.f, a3 = 0.f;
        const float* rowb = sH + o * CH_STRIDE + (py + DH0) * HSTR + qx4;
#pragma unroll
        for (int d = 0; d < NDH; d++) {
            float win[12];
            load_win(win, rowb + d * HSTR);
#pragma unroll
            for (int dw = 0; dw < 7; dw++) {
                a0 = fmaf(wt[d * 7 + dw][0], win[dw + 0], a0);
                a1 = fmaf(wt[d * 7 + dw][1], win[dw + 1], a1);
                a2 = fmaf(wt[d * 7 + dw][2], win[dw + 2], a2);
                a3 = fmaf(wt[d * 7 + dw][3], win[dw + 3], a3);
            }
        }
        pbuf[(g * 8 + o) * 64 + quad] = make_float4(a0, a1, a2, a3);
    }
}

#define ATTN_SMEM ((8 * CH_STRIDE + 8192) * 4)   // 66560 B

__global__ __launch_bounds__(256, 2) void attn_kernel(
    const float* __restrict__ x, float* __restrict__ out)
{
    extern __shared__ float smem[];
    float*  sH   = smem;                       // 8448 floats
    float*  uni  = smem + 8 * CH_STRIDE;       // union: sX / xch / pbuf
    float*  sX   = uni;                        // 2048 floats (Phase A)
    float4* xch  = (float4*)uni;               // 256 float4 (softmax)
    float4* pbuf = (float4*)uni;               // 2048 float4 (Phase B)

    const int tx   = threadIdx.x;
    const int quad = tx & 63;
    const int g    = tx >> 6;
    const int py   = quad >> 2;
    const int qx4  = (quad & 3) * 4;
    const int b  = blockIdx.z;
    const int h0 = blockIdx.y * 16, w0 = blockIdx.x * 16;

    const float* yb  = g_y + (size_t)b * C_ * HW_;
    const float* vb  = g_v + (size_t)b * C_ * HW_;
    const float* xbb = x + (size_t)b * C_ * HW_;

    const int NT = (g < 3) ? 14 : 7;

    float s[14][4];
#pragma unroll
    for (int r = 0; r < 14; r++)
#pragma unroll
        for (int p = 0; p < 4; p++) s[r][p] = 0.0f;

    // ---------------- Phase A: scores ----------------
    for (int ch0 = 0; ch0 < 64; ch0 += 8) {
        fill_halo(sH, yb, ch0, h0, w0, tx);
        for (int i = tx; i < 2048; i += 256) {
            const int cc = i >> 8, px = i & 255;
            sX[i] = xbb[(size_t)(ch0 + cc) * HW_ + (h0 + (px >> 4)) * W_ + w0 + (px & 15)];
        }
        __syncthreads();
        if      (g == 0) score_accum<2, 0>(s, sH, sX, quad, py, qx4);
        else if (g == 1) score_accum<2, 2>(s, sH, sX, quad, py, qx4);
        else if (g == 2) score_accum<2, 4>(s, sH, sX, quad, py, qx4);
        else             score_accum<1, 6>(s, sH, sX, quad, py, qx4);
        __syncthreads();
    }

    // ---------------- Softmax (4-way cross-group reduction) ----------------
    float4 pm = make_float4(-1e30f, -1e30f, -1e30f, -1e30f);
    for (int r = 0; r < NT; r++) {
        pm.x = fmaxf(pm.x, s[r][0]); pm.y = fmaxf(pm.y, s[r][1]);
        pm.z = fmaxf(pm.z, s[r][2]); pm.w = fmaxf(pm.w, s[r][3]);
    }
    xch[tx] = pm;
    __syncthreads();
    float4 m = xch[quad];
#pragma unroll
    for (int gg = 1; gg < 4; gg++) {
        const float4 t = xch[gg * 64 + quad];
        m.x = fmaxf(m.x, t.x); m.y = fmaxf(m.y, t.y);
        m.z = fmaxf(m.z, t.z); m.w = fmaxf(m.w, t.w);
    }
    __syncthreads();

    float4 ps = make_float4(0.f, 0.f, 0.f, 0.f);
    for (int r = 0; r < NT; r++) {
        s[r][0] = __expf(s[r][0] - m.x); ps.x += s[r][0];
        s[r][1] = __expf(s[r][1] - m.y); ps.y += s[r][1];
        s[r][2] = __expf(s[r][2] - m.z); ps.z += s[r][2];
        s[r][3] = __expf(s[r][3] - m.w); ps.w += s[r][3];
    }
    xch[tx] = ps;
    __syncthreads();
    float4 sum = xch[quad];
#pragma unroll
    for (int gg = 1; gg < 4; gg++) {
        const float4 t = xch[gg * 64 + quad];
        sum.x += t.x; sum.y += t.y; sum.z += t.z; sum.w += t.w;
    }
    const float4 inv = make_float4(__frcp_rn(sum.x), __frcp_rn(sum.y),
                                   __frcp_rn(sum.z), __frcp_rn(sum.w));
    for (int r = 0; r < NT; r++) {
        s[r][0] *= inv.x; s[r][1] *= inv.y; s[r][2] *= inv.z; s[r][3] *= inv.w;
    }
    __syncthreads();   // xch dead before pbuf reuse

    // ---------------- Phase B: weighting ----------------
    float* outb = out + (size_t)b * O_ * HW_;
    for (int ch0 = 0; ch0 < 64; ch0 += 8) {
        fill_halo(sH, vb, ch0, h0, w0, tx);
        __syncthreads();

        if      (g == 0) weight_chunk<2, 0>(s, sH, pbuf, g, quad, py, qx4);
        else if (g == 1) weight_chunk<2, 2>(s, sH, pbuf, g, quad, py, qx4);
        else if (g == 2) weight_chunk<2, 4>(s, sH, pbuf, g, quad, py, qx4);
        else             weight_chunk<1, 6>(s, sH, pbuf, g, quad, py, qx4);
        __syncthreads();

        // Combine 4 group partials: 512 (o, quad) items over 256 threads.
#pragma unroll
        for (int it = tx; it < 512; it += 256) {
            const int o  = it >> 6;
            const int qd = it & 63;
            const float4 t0 = pbuf[(0 * 8 + o) * 64 + qd];
            const float4 t1 = pbuf[(1 * 8 + o) * 64 + qd];
            const float4 t2 = pbuf[(2 * 8 + o) * 64 + qd];
            const float4 t3 = pbuf[(3 * 8 + o) * 64 + qd];
            const int pyq = qd >> 2, qxq = (qd & 3) * 4;
            *(float4*)(outb + (size_t)(ch0 + o) * HW_ + (h0 + pyq) * W_ + w0 + qxq) =
                make_float4(t0.x + t1.x + t2.x + t3.x,
                            t0.y + t1.y + t2.y + t3.y,
                            t0.z + t1.z + t2.z + t3.z,
                            t0.w + t1.w + t2.w + t3.w);
        }
        __syncthreads();
    }
}

// ---------------------------------------------------------------------------
extern "C" void kernel_launch(void* const* d_in, const int* in_sizes, int n_in,
                              void* d_out, int out_size)
{
    const float* x  = (const float*)d_in[0];
    const float* W1 = (const float*)d_in[1];
    const float* W2 = (const float*)d_in[2];
    const float* W3 = (const float*)d_in[3];
    float* out = (float*)d_out;
    (void)in_sizes; (void)n_in; (void)out_size;

    cudaFuncSetAttribute(attn_kernel,
                         cudaFuncAttributeMaxDynamicSharedMemorySize, ATTN_SMEM);

    mat_kernel<<<1, 256>>>(W1, W2);
    qkv_kernel<<<dim3(HW_ / 128, B_, 2), 256>>>(x, W3);
    attn_kernel<<<dim3(W_ / 16, H_ / 16, B_), 256, ATTN_SMEM>>>(x, out);
}

// round 7
// speedup vs baseline: 1.3169x; 1.3169x over previous
#include <cuda_runtime.h>
#include <cuda_bf16.h>

#define B_   8
#define C_   64
#define O_   64
#define H_   128
#define W_   128
#define HW_  16384
#define PAD_ 3
#define R_   49
#define HSTR 48                 // halo row stride (floats): conflict-free LDS.128 phases
#define CH_STRIDE (22 * HSTR)   // 1056 floats per halo channel
#define HALO_F (8 * CH_STRIDE)  // 8448 floats per halo buffer

// smem layout (floats): sH0 | sH1 | pbuf-region(8192, aliased by sX0/sX1/xch)
#define SH0_OFF  0
#define SH1_OFF  HALO_F
#define PB_OFF   (2 * HALO_F)
#define SX0_OFF  PB_OFF
#define SX1_OFF  (PB_OFF + 2048)
#define ATTN_SMEM ((2 * HALO_F + 8192) * 4)   // 100352 B

// Scratch (device globals)
__device__ float g_y[B_ * C_ * HW_];     // y = (W1^T W2) x
__device__ float g_v[B_ * C_ * HW_];     // v = W3 x
__device__ float g_M[64 * 64];           // M = W1^T W2

// -------------------- f32x2 helpers (qkv only) --------------------
__device__ __forceinline__ unsigned long long pk2(float lo, float hi) {
    unsigned long long r;
    asm("mov.b64 %0, {%1, %2};" : "=l"(r) : "f"(lo), "f"(hi));
    return r;
}
__device__ __forceinline__ void fma2(unsigned long long& d,
                                     unsigned long long a, unsigned long long b) {
    asm("fma.rn.f32x2 %0, %1, %2, %0;" : "+l"(d) : "l"(a), "l"(b));
}
__device__ __forceinline__ void upk2(unsigned long long v, float& lo, float& hi) {
    asm("mov.b64 {%0, %1}, %2;" : "=f"(lo), "=f"(hi) : "l"(v));
}

// -------------------- cp.async helpers --------------------
__device__ __forceinline__ void cpa4(float* smem_dst, const float* gsrc) {
    unsigned sa = (unsigned)__cvta_generic_to_shared(smem_dst);
    asm volatile("cp.async.ca.shared.global [%0], [%1], 4;" :: "r"(sa), "l"(gsrc));
}
__device__ __forceinline__ void cpa16(float* smem_dst, const float* gsrc) {
    unsigned sa = (unsigned)__cvta_generic_to_shared(smem_dst);
    asm volatile("cp.async.cg.shared.global [%0], [%1], 16;" :: "r"(sa), "l"(gsrc));
}
__device__ __forceinline__ void cpa_commit() {
    asm volatile("cp.async.commit_group;" ::: "memory");
}
template<int N>
__device__ __forceinline__ void cpa_wait() {
    asm volatile("cp.async.wait_group %0;" :: "n"(N) : "memory");
}

// ---------------------------------------------------------------------------
// Kernel 0: M = W1^T W2   (64x64x64), parallel: 16 blocks, 1 elem/thread.
// ---------------------------------------------------------------------------
__global__ __launch_bounds__(256) void mat_kernel(
    const float* __restrict__ W1, const float* __restrict__ W2)
{
    const int gi = blockIdx.x * 256 + threadIdx.x;
    const int c = gi >> 6, cp = gi & 63;
    float acc = 0.0f;
#pragma unroll 8
    for (int o = 0; o < 64; o++)
        acc = fmaf(W1[o * 64 + c], W2[o * 64 + cp], acc);
    g_M[c * 64 + cp] = acc;
}

// ---------------------------------------------------------------------------
// Kernel 1: y = M x (z=0), v = W3 x (z=1). f32x2 packed over out-pairs.
// ---------------------------------------------------------------------------
__device__ __forceinline__ int wswz(int c, int o) {
    return c * 64 + (o ^ ((c << 1) & 63));
}

__global__ __launch_bounds__(256) void qkv_kernel(
    const float* __restrict__ x, const float* __restrict__ W3)
{
    __shared__ __align__(16) float sX[64 * 128];   // 32 KB
    __shared__ __align__(16) float sWp[64 * 64];   // 16 KB

    const int b = blockIdx.y, z = blockIdx.z;
    const float* Wm = (z == 0) ? g_M : W3;
    float* outp     = (z == 0) ? g_y : g_v;

    const int tx = threadIdx.x;
    const int n0 = blockIdx.x * 128;

    for (int i = tx; i < 4096; i += 256) {
        const int o = i >> 6, c = i & 63;
        sWp[wswz(c, o)] = Wm[i];
    }
    const float* xb = x + (size_t)b * C_ * HW_ + n0;
    for (int i = tx; i < 2048; i += 256) {
        const int c = i >> 5, j = i & 31;
        *(float4*)&sX[c * 128 + j * 4] = *(const float4*)(xb + (size_t)c * HW_ + j * 4);
    }
    __syncthreads();

    const int pp = tx & 31;
    const int oo = (tx >> 5) * 8;

    unsigned long long acc[4][4];
#pragma unroll
    for (int p = 0; p < 4; p++)
#pragma unroll
        for (int j = 0; j < 4; j++) acc[p][j] = 0ULL;

#pragma unroll 8
    for (int c = 0; c < 64; c++) {
        const float2 xa = *(const float2*)&sX[c * 128 + 2 * pp];
        const float2 xc = *(const float2*)&sX[c * 128 + 64 + 2 * pp];
        const unsigned long long d0 = pk2(xa.x, xa.x);
        const unsigned long long d1 = pk2(xa.y, xa.y);
        const unsigned long long d2 = pk2(xc.x, xc.x);
        const unsigned long long d3 = pk2(xc.y, xc.y);
#pragma unroll
        for (int j = 0; j < 4; j++) {
            const unsigned long long w2 =
                *(const unsigned long long*)&sWp[wswz(c, oo + 2 * j)];
            fma2(acc[0][j], w2, d0);
            fma2(acc[1][j], w2, d1);
            fma2(acc[2][j], w2, d2);
            fma2(acc[3][j], w2, d3);
        }
    }

    float* ob = outp + (size_t)b * O_ * HW_ + n0;
#pragma unroll
    for (int j = 0; j < 4; j++) {
        float a0, a1, b0, b1, c0, c1, d0, d1;
        upk2(acc[0][j], a0, a1);
        upk2(acc[1][j], b0, b1);
        upk2(acc[2][j], c0, c1);
        upk2(acc[3][j], d0, d1);
        const int o = oo + 2 * j;
        *(float2*)(ob + (size_t)o * HW_ + 2 * pp)            = make_float2(a0, b0);
        *(float2*)(ob + (size_t)o * HW_ + 64 + 2 * pp)       = make_float2(c0, d0);
        *(float2*)(ob + (size_t)(o + 1) * HW_ + 2 * pp)      = make_float2(a1, b1);
        *(float2*)(ob + (size_t)(o + 1) * HW_ + 64 + 2 * pp) = make_float2(c1, d1);
    }
}

// Load 12-float window as 3 aligned LDS.128.
__device__ __forceinline__ void load_win(float* win, const float* rp) {
    const float4 A = *(const float4*)(rp);
    const float4 Bv = *(const float4*)(rp + 4);
    const float4 Cv = *(const float4*)(rp + 8);
    win[0] = A.x;  win[1] = A.y;  win[2] = A.z;  win[3] = A.w;
    win[4] = Bv.x; win[5] = Bv.y; win[6] = Bv.z; win[7] = Bv.w;
    win[8] = Cv.x; win[9] = Cv.y; win[10] = Cv.z; win[11] = Cv.w;
}

// ---------------------------------------------------------------------------
// Fused attention: scores + softmax + weighting, cp.async double-buffered.
// 16x16 tile, 256 thr = 64 quads (4 aligned px) x 4 dh-groups (2,2,2,1 rows).
// ---------------------------------------------------------------------------
template<int NDH, int DH0>
__device__ __forceinline__ void score_accum(
    float s[][4], const float* sH, const float* sX, int quad, int py, int qx4)
{
#pragma unroll
    for (int cc = 0; cc < 8; cc++) {
        const float4 q4 = *(const float4*)&sX[cc * 256 + 4 * quad];
        const float* rowb = sH + cc * CH_STRIDE + (py + DH0) * HSTR + qx4;
#pragma unroll
        for (int d = 0; d < NDH; d++) {
            float win[12];
            load_win(win, rowb + d * HSTR);
#pragma unroll
            for (int dw = 0; dw < 7; dw++) {
                s[d * 7 + dw][0] = fmaf(q4.x, win[dw + 0], s[d * 7 + dw][0]);
                s[d * 7 + dw][1] = fmaf(q4.y, win[dw + 1], s[d * 7 + dw][1]);
                s[d * 7 + dw][2] = fmaf(q4.z, win[dw + 2], s[d * 7 + dw][2]);
                s[d * 7 + dw][3] = fmaf(q4.w, win[dw + 3], s[d * 7 + dw][3]);
            }
        }
    }
}

template<int NDH, int DH0>
__device__ __forceinline__ void weight_chunk(
    const float wt[][4], const float* sH, float4* pbuf,
    int g, int quad, int py, int qx4)
{
#pragma unroll
    for (int o = 0; o < 8; o++) {
        float a0 = 0.f, a1 = 0.f, a2 = 0.f, a3 = 0.f;
        const float* rowb = sH + o * CH_STRIDE + (py + DH0) * HSTR + qx4;
#pragma unroll
        for (int d = 0; d < NDH; d++) {
            float win[12];
            load_win(win, rowb + d * HSTR);
#pragma unroll
            for (int dw = 0; dw < 7; dw++) {
                a0 = fmaf(wt[d * 7 + dw][0], win[dw + 0], a0);
                a1 = fmaf(wt[d * 7 + dw][1], win[dw + 1], a1);
                a2 = fmaf(wt[d * 7 + dw][2], win[dw + 2], a2);
                a3 = fmaf(wt[d * 7 + dw][3], win[dw + 3], a3);
            }
        }
        pbuf[(g * 8 + o) * 64 + quad] = make_float4(a0, a1, a2, a3);
    }
}

__global__ __launch_bounds__(256, 2) void attn_kernel(
    const float* __restrict__ x, float* __restrict__ out)
{
    extern __shared__ __align__(16) float smem[];
    float4* pbuf = (float4*)(smem + PB_OFF);
    float4* xch  = (float4*)(smem + PB_OFF);

    const int tx   = threadIdx.x;
    const int quad = tx & 63;
    const int g    = tx >> 6;
    const int py   = quad >> 2;
    const int qx4  = (quad & 3) * 4;
    const int b  = blockIdx.z;
    const int h0 = blockIdx.y * 16, w0 = blockIdx.x * 16;

    const float* yb  = g_y + (size_t)b * C_ * HW_;
    const float* vb  = g_v + (size_t)b * C_ * HW_;
    const float* xbb = x + (size_t)b * C_ * HW_ + h0 * W_ + w0;

    // ---- Precompute fill descriptors (all div/mod done ONCE) ----
    // Halo cells j1=tx (<484 always), j2=tx+256 (may be >=484)
    const int j1 = tx;
    const int r1 = j1 / 22, cl1 = j1 - 22 * r1;
    const int hh1 = h0 + r1 - PAD_, ww1 = w0 + cl1 - PAD_;
    const bool v1 = (hh1 >= 0 && hh1 < H_ && ww1 >= 0 && ww1 < W_);
    const int so1 = r1 * HSTR + cl1;
    const int gp1 = v1 ? (hh1 * W_ + ww1 - h0 * W_ - w0) : 0;   // rel to xbb-style base
    const int j2 = tx + 256;
    const bool has2 = (j2 < 484);
    const int r2 = j2 / 22, cl2 = j2 - 22 * r2;
    const int hh2 = h0 + r2 - PAD_, ww2 = w0 + cl2 - PAD_;
    const bool v2 = has2 && (hh2 >= 0 && hh2 < H_ && ww2 >= 0 && ww2 < W_);
    const int so2 = r2 * HSTR + cl2;
    const int gp2 = v2 ? (hh2 * W_ + ww2 - h0 * W_ - w0) : 0;
    // sX descriptors: float4 items i0=tx, i1=tx+256 of 512
    const int i0cc = tx >> 6,            i0r = tx & 63;
    const int i1cc = (tx + 256) >> 6,    i1r = (tx + 256) & 63;
    const int sxg0 = i0cc * HW_ + (i0r >> 2) * W_ + (i0r & 3) * 4;
    const int sxg1 = i1cc * HW_ + (i1r >> 2) * W_ + (i1r & 3) * 4;
    const int sxs0 = i0cc * 256 + i0r * 4;
    const int sxs1 = i1cc * 256 + i1r * 4;

    // ---- Zero OOB halo cells once (chunk-invariant positions) ----
#pragma unroll
    for (int bf = 0; bf < 2; bf++) {
        float* sH = smem + (bf ? SH1_OFF : SH0_OFF);
        if (!v1) {
#pragma unroll
            for (int cc = 0; cc < 8; cc++) sH[cc * CH_STRIDE + so1] = 0.0f;
        }
        if (has2 && !v2) {
#pragma unroll
            for (int cc = 0; cc < 8; cc++) sH[cc * CH_STRIDE + so2] = 0.0f;
        }
    }

    // ---- Prefetch helper (chunk k: 0..7 = y(+sX), 8..15 = v) ----
    const float* ybase = yb + h0 * W_ + w0;   // halo offsets gp are relative to this
    const float* vbase = vb + h0 * W_ + w0;
    auto prefetch = [&](int k) {
        const int ch0 = (k & 7) * 8;
        const float* src = ((k < 8) ? ybase : vbase) + (size_t)ch0 * HW_;
        float* sH = smem + ((k & 1) ? SH1_OFF : SH0_OFF);
        if (v1) {
#pragma unroll
            for (int cc = 0; cc < 8; cc++)
                cpa4(&sH[cc * CH_STRIDE + so1], src + (size_t)cc * HW_ + gp1);
        }
        if (v2) {
#pragma unroll
            for (int cc = 0; cc < 8; cc++)
                cpa4(&sH[cc * CH_STRIDE + so2], src + (size_t)cc * HW_ + gp2);
        }
        if (k < 8) {
            float* sX = smem + ((k & 1) ? SX1_OFF : SX0_OFF);
            const float* xs = xbb + (size_t)ch0 * HW_;
            cpa16(&sX[sxs0], xs + sxg0);
            cpa16(&sX[sxs1], xs + sxg1);
        }
        cpa_commit();
    };

    prefetch(0);
    prefetch(1);

    const int NT = (g < 3) ? 14 : 7;

    float s[14][4];
#pragma unroll
    for (int r = 0; r < 14; r++)
#pragma unroll
        for (int p = 0; p < 4; p++) s[r][p] = 0.0f;

    // ---------------- Phase A: scores ----------------
    for (int i = 0; i < 8; i++) {
        cpa_wait<1>();
        __syncthreads();
        const float* sH = smem + ((i & 1) ? SH1_OFF : SH0_OFF);
        const float* sX = smem + ((i & 1) ? SX1_OFF : SX0_OFF);
        if      (g == 0) score_accum<2, 0>(s, sH, sX, quad, py, qx4);
        else if (g == 1) score_accum<2, 2>(s, sH, sX, quad, py, qx4);
        else if (g == 2) score_accum<2, 4>(s, sH, sX, quad, py, qx4);
        else             score_accum<1, 6>(s, sH, sX, quad, py, qx4);
        __syncthreads();
        prefetch(i + 2);   // i+2 <= 9 here
    }

    // ---------------- Softmax (overlaps v-chunk 0/1 prefetch) ----------------
    float4 pm = make_float4(-1e30f, -1e30f, -1e30f, -1e30f);
    for (int r = 0; r < NT; r++) {
        pm.x = fmaxf(pm.x, s[r][0]); pm.y = fmaxf(pm.y, s[r][1]);
        pm.z = fmaxf(pm.z, s[r][2]); pm.w = fmaxf(pm.w, s[r][3]);
    }
    xch[tx] = pm;
    __syncthreads();
    float4 m = xch[quad];
#pragma unroll
    for (int gg = 1; gg < 4; gg++) {
        const float4 t = xch[gg * 64 + quad];
        m.x = fmaxf(m.x, t.x); m.y = fmaxf(m.y, t.y);
        m.z = fmaxf(m.z, t.z); m.w = fmaxf(m.w, t.w);
    }
    __syncthreads();

    float4 ps = make_float4(0.f, 0.f, 0.f, 0.f);
    for (int r = 0; r < NT; r++) {
        s[r][0] = __expf(s[r][0] - m.x); ps.x += s[r][0];
        s[r][1] = __expf(s[r][1] - m.y); ps.y += s[r][1];
        s[r][2] = __expf(s[r][2] - m.z); ps.z += s[r][2];
        s[r][3] = __expf(s[r][3] - m.w); ps.w += s[r][3];
    }
    xch[tx] = ps;
    __syncthreads();
    float4 sum = xch[quad];
#pragma unroll
    for (int gg = 1; gg < 4; gg++) {
        const float4 t = xch[gg * 64 + quad];
        sum.x += t.x; sum.y += t.y; sum.z += t.z; sum.w += t.w;
    }
    const float4 inv = make_float4(__frcp_rn(sum.x), __frcp_rn(sum.y),
                                   __frcp_rn(sum.z), __frcp_rn(sum.w));
    for (int r = 0; r < NT; r++) {
        s[r][0] *= inv.x; s[r][1] *= inv.y; s[r][2] *= inv.z; s[r][3] *= inv.w;
    }
    __syncthreads();   // xch dead before pbuf reuse

    // ---------------- Phase B: weighting ----------------
    float* outb = out + (size_t)b * O_ * HW_;
    for (int i = 8; i < 16; i++) {
        if (i == 15) cpa_wait<0>(); else cpa_wait<1>();
        __syncthreads();
        const float* sH = smem + ((i & 1) ? SH1_OFF : SH0_OFF);
        const int ch0 = (i & 7) * 8;
        if      (g == 0) weight_chunk<2, 0>(s, sH, pbuf, g, quad, py, qx4);
        else if (g == 1) weight_chunk<2, 2>(s, sH, pbuf, g, quad, py, qx4);
        else if (g == 2) weight_chunk<2, 4>(s, sH, pbuf, g, quad, py, qx4);
        else             weight_chunk<1, 6>(s, sH, pbuf, g, quad, py, qx4);
        __syncthreads();

#pragma unroll
        for (int it = tx; it < 512; it += 256) {
            const int o  = it >> 6;
            const int qd = it & 63;
            const float4 t0 = pbuf[(0 * 8 + o) * 64 + qd];
            const float4 t1 = pbuf[(1 * 8 + o) * 64 + qd];
            const float4 t2 = pbuf[(2 * 8 + o) * 64 + qd];
            const float4 t3 = pbuf[(3 * 8 + o) * 64 + qd];
            const int pyq = qd >> 2, qxq = (qd & 3) * 4;
            *(float4*)(outb + (size_t)(ch0 + o) * HW_ + (h0 + pyq) * W_ + w0 + qxq) =
                make_float4(t0.x + t1.x + t2.x + t3.x,
                            t0.y + t1.y + t2.y + t3.y,
                            t0.z + t1.z + t2.z + t3.z,
                            t0.w + t1.w + t2.w + t3.w);
        }
        if (i + 2 < 16) prefetch(i + 2);
    }
}

// ---------------------------------------------------------------------------
extern "C" void kernel_launch(void* const* d_in, const int* in_sizes, int n_in,
                              void* d_out, int out_size)
{
    const float* x  = (const float*)d_in[0];
    const float* W1 = (const float*)d_in[1];
    const float* W2 = (const float*)d_in[2];
    const float* W3 = (const float*)d_in[3];
    float* out = (float*)d_out;
    (void)in_sizes; (void)n_in; (void)out_size;

    cudaFuncSetAttribute(attn_kernel,
                         cudaFuncAttributeMaxDynamicSharedMemorySize, ATTN_SMEM);

    mat_kernel<<<16, 256>>>(W1, W2);
    qkv_kernel<<<dim3(HW_ / 128, B_, 2), 256>>>(x, W3);
    attn_kernel<<<dim3(W_ / 16, H_ / 16, B_), 256, ATTN_SMEM>>>(x, out);
}